// round 3
// baseline (speedup 1.0000x reference)
#include <cuda_runtime.h>
#include <cuda_bf16.h>
#include <cstdint>

#define N_NODES 100000
#define N_EDGES 500000
#define N_REL 4
#define N_LAYERS 4
#define IN_FEAT 64
#define EMB 128
#define N_GRAPHS 64

// ---------------- scratch (device globals; no allocation allowed) ----------------
__device__ float g_h[(size_t)N_NODES * EMB];     // node features
__device__ float g_out[(size_t)N_NODES * EMB];   // layer accumulator
__device__ float g_tmp[(size_t)N_NODES * EMB];   // per-relation conv output
__device__ int   g_csr_src[(size_t)N_REL * N_EDGES];
__device__ int   g_deg[(size_t)N_REL * N_NODES];
__device__ int   g_off[(size_t)N_REL * (N_NODES + 1)];
__device__ int   g_cur[(size_t)N_REL * N_NODES];

// ---------------- utility kernels ----------------
__global__ void zero_int_kernel(int* p, int n) {
    int i = blockIdx.x * blockDim.x + threadIdx.x;
    if (i < n) p[i] = 0;
}
__global__ void zero_float_kernel(float* p, int n) {
    int i = blockIdx.x * blockDim.x + threadIdx.x;
    if (i < n) p[i] = 0.0f;
}
__global__ void copy_int_kernel(const int* __restrict__ a, int* __restrict__ b, int n) {
    int i = blockIdx.x * blockDim.x + threadIdx.x;
    if (i < n) b[i] = a[i];
}

// histogram of destination degrees
__global__ void hist_kernel(const int* __restrict__ dst, int* __restrict__ deg, int e) {
    int i = blockIdx.x * blockDim.x + threadIdx.x;
    if (i < e) atomicAdd(&deg[dst[i]], 1);
}

// single-block exclusive scan over n entries; off has n+1 slots
__global__ void scan_kernel(const int* __restrict__ deg, int* __restrict__ off, int n) {
    __shared__ int sums[1024];
    int t = threadIdx.x;
    int chunk = (n + 1023) >> 10;
    int start = t * chunk;
    int end = min(start + chunk, n);
    int s = 0;
    for (int i = start; i < end; i++) { off[i] = s; s += deg[i]; }
    sums[t] = s;
    __syncthreads();
    // Hillis-Steele inclusive scan
    for (int d = 1; d < 1024; d <<= 1) {
        int v = (t >= d) ? sums[t - d] : 0;
        __syncthreads();
        sums[t] += v;
        __syncthreads();
    }
    int prefix = (t == 0) ? 0 : sums[t - 1];
    for (int i = start; i < end; i++) off[i] += prefix;
    if (t == 1023) off[n] = sums[1023];
}

// fill CSR: csr[pos] = src for each edge, bucketed by dst
__global__ void fill_kernel(const int* __restrict__ src, const int* __restrict__ dst,
                            int* __restrict__ cur, int* __restrict__ csr, int e) {
    int i = blockIdx.x * blockDim.x + threadIdx.x;
    if (i < e) {
        int d = dst[i];
        int pos = atomicAdd(&cur[d], 1);
        csr[pos] = src[i];
    }
}

// ---------------- GEMM: C[M,128] = A[M,K] @ W[K,128] (+ bias) ----------------
// BM=128 BN=128 BK=16, 256 threads, 8x8 per thread.
__global__ __launch_bounds__(256) void gemm_kernel(
    const float* __restrict__ A, const float* __restrict__ W,
    const float* __restrict__ bias, float* __restrict__ C, int M, int K)
{
    const int BM = 128, BN = 128, BK = 16, TM = 8, TN = 8;
    __shared__ float As[BK][BM];
    __shared__ float Bs[BK][BN];

    int tid = threadIdx.x;
    int tr = tid >> 4;      // 0..15
    int tc = tid & 15;      // 0..15
    int row0 = blockIdx.x * BM;

    float acc[TM][TN];
#pragma unroll
    for (int m = 0; m < TM; m++)
#pragma unroll
        for (int n = 0; n < TN; n++) acc[m][n] = 0.0f;

    for (int k0 = 0; k0 < K; k0 += BK) {
        // A tile load: 128x16 floats = 512 float4, each thread 2
#pragma unroll
        for (int i = 0; i < 2; i++) {
            int idx = tid * 2 + i;
            int r = idx >> 2;
            int kq = (idx & 3) << 2;
            int grow = row0 + r;
            float4 v = make_float4(0.f, 0.f, 0.f, 0.f);
            if (grow < M)
                v = *(const float4*)(A + (size_t)grow * K + k0 + kq);
            As[kq + 0][r] = v.x;
            As[kq + 1][r] = v.y;
            As[kq + 2][r] = v.z;
            As[kq + 3][r] = v.w;
        }
        // B tile load: 16x128 floats = 512 float4, each thread 2
#pragma unroll
        for (int i = 0; i < 2; i++) {
            int idx = tid * 2 + i;
            int r = idx >> 5;
            int cq = (idx & 31) << 2;
            float4 v = *(const float4*)(W + (size_t)(k0 + r) * BN + cq);
            *(float4*)(&Bs[r][cq]) = v;
        }
        __syncthreads();

#pragma unroll
        for (int kk = 0; kk < BK; kk++) {
            float a[TM], b[TN];
            *(float4*)&a[0] = *(const float4*)&As[kk][tr * TM];
            *(float4*)&a[4] = *(const float4*)&As[kk][tr * TM + 4];
            *(float4*)&b[0] = *(const float4*)&Bs[kk][tc * TN];
            *(float4*)&b[4] = *(const float4*)&Bs[kk][tc * TN + 4];
#pragma unroll
            for (int m = 0; m < TM; m++)
#pragma unroll
                for (int n = 0; n < TN; n++)
                    acc[m][n] = fmaf(a[m], b[n], acc[m][n]);
        }
        __syncthreads();
    }

#pragma unroll
    for (int m = 0; m < TM; m++) {
        int grow = row0 + tr * TM + m;
        if (grow >= M) continue;
#pragma unroll
        for (int n = 0; n < TN; n += 4) {
            int col = tc * TN + n;
            float4 v;
            v.x = acc[m][n + 0];
            v.y = acc[m][n + 1];
            v.z = acc[m][n + 2];
            v.w = acc[m][n + 3];
            if (bias) {
                v.x += bias[col + 0];
                v.y += bias[col + 1];
                v.z += bias[col + 2];
                v.w += bias[col + 3];
            }
            *(float4*)(C + (size_t)grow * BN + col) = v;
        }
    }
}

// ---------------- aggregation: out[n] += max over incoming edges of msg[src]; optional relu->hOut
__global__ __launch_bounds__(128) void aggregate_kernel(
    const float* __restrict__ msg, const int* __restrict__ off,
    const int* __restrict__ csr, float* __restrict__ outbuf,
    float* __restrict__ hOut, int do_relu)
{
    int nIdx = blockIdx.x;
    int f = threadIdx.x;
    int s = off[nIdx];
    int e = off[nIdx + 1];
    float m = -3.402823466e38f;
    for (int i = s; i < e; i++) {
        int src = __ldg(&csr[i]);
        m = fmaxf(m, __ldg(&msg[(size_t)src * EMB + f]));
    }
    float contrib = (e > s) ? m : 0.0f;
    float v = outbuf[(size_t)nIdx * EMB + f] + contrib;
    if (do_relu)
        hOut[(size_t)nIdx * EMB + f] = fmaxf(v, 0.0f);
    else
        outbuf[(size_t)nIdx * EMB + f] = v;
}

// ---------------- global add pool: out[g] = sum over nodes with batch==g ----------------
__global__ __launch_bounds__(128) void pool_kernel(
    const float* __restrict__ h, const int* __restrict__ batch,
    float* __restrict__ out, int n)
{
    const int NPB = 256;
    int f = threadIdx.x;
    int n0 = blockIdx.x * NPB;
    if (n0 >= n) return;
    int nend = min(n0 + NPB, n);
    float acc = 0.0f;
    int cur = batch[n0];
    for (int i = n0; i < nend; i++) {
        int b = batch[i];
        if (b != cur) {
            atomicAdd(&out[(size_t)cur * EMB + f], acc);
            acc = 0.0f;
            cur = b;
        }
        acc += h[(size_t)i * EMB + f];
    }
    atomicAdd(&out[(size_t)cur * EMB + f], acc);
}

// ---------------- host launch ----------------
extern "C" void kernel_launch(void* const* d_in, const int* in_sizes, int n_in,
                              void* d_out, int out_size)
{
    const float* x      = (const float*)d_in[0];
    const int*   ei[N_REL] = { (const int*)d_in[1], (const int*)d_in[2],
                               (const int*)d_in[3], (const int*)d_in[4] };
    const int*   batch  = (const int*)d_in[5];
    const float* emb_w  = (const float*)d_in[6];
    const float* emb_b  = (const float*)d_in[7];
    const float* root_w = (const float*)d_in[8];
    const float* root_b = (const float*)d_in[9];
    const float* conv_w = (const float*)d_in[10];
    float* out = (float*)d_out;

    void *p_h, *p_out, *p_tmp, *p_csr, *p_deg, *p_off, *p_cur;
    cudaGetSymbolAddress(&p_h, g_h);
    cudaGetSymbolAddress(&p_out, g_out);
    cudaGetSymbolAddress(&p_tmp, g_tmp);
    cudaGetSymbolAddress(&p_csr, g_csr_src);
    cudaGetSymbolAddress(&p_deg, g_deg);
    cudaGetSymbolAddress(&p_off, g_off);
    cudaGetSymbolAddress(&p_cur, g_cur);
    float* h_buf   = (float*)p_h;
    float* out_buf = (float*)p_out;
    float* tmp_buf = (float*)p_tmp;
    int* csr = (int*)p_csr;
    int* deg = (int*)p_deg;
    int* off = (int*)p_off;
    int* cur = (int*)p_cur;

    const int EB = (N_EDGES + 255) / 256;
    const int GB = (N_NODES + 127) / 128;   // GEMM blocks

    // ---- CSR build (per relation) ----
    zero_int_kernel<<<(N_REL * N_NODES + 255) / 256, 256>>>(deg, N_REL * N_NODES);
    for (int r = 0; r < N_REL; r++)
        hist_kernel<<<EB, 256>>>(ei[r] + N_EDGES, deg + (size_t)r * N_NODES, N_EDGES);
    for (int r = 0; r < N_REL; r++)
        scan_kernel<<<1, 1024>>>(deg + (size_t)r * N_NODES,
                                 off + (size_t)r * (N_NODES + 1), N_NODES);
    for (int r = 0; r < N_REL; r++)
        copy_int_kernel<<<(N_NODES + 255) / 256, 256>>>(
            off + (size_t)r * (N_NODES + 1), cur + (size_t)r * N_NODES, N_NODES);
    for (int r = 0; r < N_REL; r++)
        fill_kernel<<<EB, 256>>>(ei[r], ei[r] + N_EDGES,
                                 cur + (size_t)r * N_NODES,
                                 csr + (size_t)r * N_EDGES, N_EDGES);

    // ---- embed: h = x @ emb_w + emb_b ----
    gemm_kernel<<<GB, 256>>>(x, emb_w, emb_b, h_buf, N_NODES, IN_FEAT);

    // ---- layers ----
    for (int l = 0; l < N_LAYERS; l++) {
        gemm_kernel<<<GB, 256>>>(h_buf, root_w + (size_t)l * EMB * EMB,
                                 root_b + (size_t)l * EMB, out_buf, N_NODES, EMB);
        for (int r = 0; r < N_REL; r++) {
            gemm_kernel<<<GB, 256>>>(h_buf,
                                     conv_w + ((size_t)l * N_REL + r) * EMB * EMB,
                                     nullptr, tmp_buf, N_NODES, EMB);
            aggregate_kernel<<<N_NODES, 128>>>(
                tmp_buf, off + (size_t)r * (N_NODES + 1),
                csr + (size_t)r * N_EDGES, out_buf, h_buf, (r == N_REL - 1) ? 1 : 0);
        }
    }

    // ---- global add pool ----
    zero_float_kernel<<<(N_GRAPHS * EMB + 255) / 256, 256>>>(out, N_GRAPHS * EMB);
    pool_kernel<<<(N_NODES + 255) / 256, 128>>>(h_buf, batch, out, N_NODES);
}

// round 5
// speedup vs baseline: 1.1624x; 1.1624x over previous
#include <cuda_runtime.h>
#include <cuda_bf16.h>
#include <cstdint>

#define N_NODES 100000
#define N_EDGES 500000
#define N_REL 4
#define N_LAYERS 4
#define IN_FEAT 64
#define EMB 128
#define N_GRAPHS 64

// ---------------- scratch (device globals; no allocation allowed) ----------------
__device__ float g_h[(size_t)N_NODES * EMB];                 // node features fp32 (for pool)
__device__ float g_out[(size_t)N_NODES * EMB];               // layer accumulator
__device__ float g_tmp[(size_t)N_REL * N_NODES * EMB];       // per-relation conv outputs
__device__ __nv_bfloat16 g_h_hi[(size_t)N_NODES * EMB];
__device__ __nv_bfloat16 g_h_lo[(size_t)N_NODES * EMB];
__device__ __nv_bfloat16 g_x_hi[(size_t)N_NODES * IN_FEAT];
__device__ __nv_bfloat16 g_x_lo[(size_t)N_NODES * IN_FEAT];
// 21 weight matrices, stored transposed [N=128][K=128] bf16 row-major (k contiguous)
// slot 0 = emb (K rows 64..127 zero), 1..4 = root, 5..20 = conv (l*4+r)
__device__ __nv_bfloat16 g_w_hi[(size_t)21 * 128 * 128];
__device__ __nv_bfloat16 g_w_lo[(size_t)21 * 128 * 128];
__device__ int   g_csr_src[(size_t)N_REL * N_EDGES];
__device__ int   g_deg[(size_t)N_REL * N_NODES];
__device__ int   g_off[(size_t)N_REL * (N_NODES + 1)];
__device__ int   g_cur[(size_t)N_REL * N_NODES];

// ---------------- warp-mma helpers (baseline PTX; valid at compute_103) ----------------
__device__ __forceinline__ uint32_t smem_u32(const void* p) {
    uint32_t a;
    asm("{ .reg .u64 t; cvta.to.shared.u64 t, %1; cvt.u32.u64 %0, t; }" : "=r"(a) : "l"(p));
    return a;
}
__device__ __forceinline__ void ldsm4(uint32_t& r0, uint32_t& r1, uint32_t& r2, uint32_t& r3,
                                      uint32_t addr) {
    asm volatile("ldmatrix.sync.aligned.m8n8.x4.shared.b16 {%0,%1,%2,%3}, [%4];"
                 : "=r"(r0), "=r"(r1), "=r"(r2), "=r"(r3) : "r"(addr));
}
__device__ __forceinline__ void mma16816(float* d, const uint32_t* a, const uint32_t* b) {
    asm volatile(
        "mma.sync.aligned.m16n8k16.row.col.f32.bf16.bf16.f32 "
        "{%0,%1,%2,%3}, {%4,%5,%6,%7}, {%8,%9}, {%0,%1,%2,%3};"
        : "+f"(d[0]), "+f"(d[1]), "+f"(d[2]), "+f"(d[3])
        : "r"(a[0]), "r"(a[1]), "r"(a[2]), "r"(a[3]), "r"(b[0]), "r"(b[1]));
}

// ---------------- utility kernels ----------------
__global__ void zero_int_kernel(int* p, int n) {
    int i = blockIdx.x * blockDim.x + threadIdx.x;
    if (i < n) p[i] = 0;
}
__global__ void zero_float_kernel(float* p, int n) {
    int i = blockIdx.x * blockDim.x + threadIdx.x;
    if (i < n) p[i] = 0.0f;
}
__global__ void copy_int_kernel(const int* __restrict__ a, int* __restrict__ b, int n) {
    int i = blockIdx.x * blockDim.x + threadIdx.x;
    if (i < n) b[i] = a[i];
}
__global__ void hist_kernel(const int* __restrict__ dst, int* __restrict__ deg, int e) {
    int i = blockIdx.x * blockDim.x + threadIdx.x;
    if (i < e) atomicAdd(&deg[dst[i]], 1);
}
__global__ void scan_kernel(const int* __restrict__ deg, int* __restrict__ off, int n) {
    __shared__ int sums[1024];
    int t = threadIdx.x;
    int chunk = (n + 1023) >> 10;
    int start = t * chunk;
    int end = min(start + chunk, n);
    int s = 0;
    for (int i = start; i < end; i++) { off[i] = s; s += deg[i]; }
    sums[t] = s;
    __syncthreads();
    for (int d = 1; d < 1024; d <<= 1) {
        int v = (t >= d) ? sums[t - d] : 0;
        __syncthreads();
        sums[t] += v;
        __syncthreads();
    }
    int prefix = (t == 0) ? 0 : sums[t - 1];
    for (int i = start; i < end; i++) off[i] += prefix;
    if (t == 1023) off[n] = sums[1023];
}
__global__ void fill_kernel(const int* __restrict__ src, const int* __restrict__ dst,
                            int* __restrict__ cur, int* __restrict__ csr, int e) {
    int i = blockIdx.x * blockDim.x + threadIdx.x;
    if (i < e) {
        int d = dst[i];
        int pos = atomicAdd(&cur[d], 1);
        csr[pos] = src[i];
    }
}

// ---------------- fp32 -> bf16 hi/lo split kernels ----------------
__global__ void split_x_kernel(const float* __restrict__ x,
                               __nv_bfloat16* __restrict__ hi,
                               __nv_bfloat16* __restrict__ lo, int n) {
    int i = blockIdx.x * blockDim.x + threadIdx.x;
    if (i >= n) return;
    float v = x[i];
    __nv_bfloat16 h = __float2bfloat16(v);
    hi[i] = h;
    lo[i] = __float2bfloat16(v - __bfloat162float(h));
}

__global__ void split_w_kernel(const float* __restrict__ emb_w,
                               const float* __restrict__ root_w,
                               const float* __restrict__ conv_w,
                               __nv_bfloat16* __restrict__ whi,
                               __nv_bfloat16* __restrict__ wlo) {
    int idx = blockIdx.x * blockDim.x + threadIdx.x;
    if (idx >= 21 * 128 * 128) return;
    int s = idx >> 14;
    int rem = idx & 16383;
    int n = rem >> 7;
    int k = rem & 127;
    float v;
    if (s == 0)      v = (k < IN_FEAT) ? emb_w[(size_t)k * EMB + n] : 0.0f;
    else if (s <= 4) v = root_w[((size_t)(s - 1) * EMB + k) * EMB + n];
    else             v = conv_w[((size_t)(s - 5) * EMB + k) * EMB + n];
    __nv_bfloat16 h = __float2bfloat16(v);
    whi[idx] = h;
    wlo[idx] = __float2bfloat16(v - __bfloat162float(h));
}

// ---------------- bf16x3 mma.sync GEMM: C[M,128] = A[M,K] @ W^T + bias ----------------
// A: bf16 hi/lo [M][K] row-major. W: transposed [128][128] bf16 (k contiguous) per slot;
// blockIdx.y selects weight slot (+y*16384) and output buffer (+y*M*N) for batched convs.
// Accumulates hi*hi + hi*lo + lo*hi in fp32 (rel err ~2^-16).
#define BK 32
#define SSTR 40   // smem row stride in bf16 elems (32 + 8 pad -> 80B rows, conflict-free)

__global__ __launch_bounds__(256, 2) void gemm_mma(
    const __nv_bfloat16* __restrict__ Ahi, const __nv_bfloat16* __restrict__ Alo,
    int M, int K,
    const __nv_bfloat16* __restrict__ Whi0, const __nv_bfloat16* __restrict__ Wlo0,
    const float* __restrict__ bias,
    float* __restrict__ C0,
    __nv_bfloat16* __restrict__ Ohi, __nv_bfloat16* __restrict__ Olo)
{
    __shared__ __nv_bfloat16 As[128 * SSTR];
    __shared__ __nv_bfloat16 Bs[128 * SSTR];

    const __nv_bfloat16* Whi = Whi0 + (size_t)blockIdx.y * 16384;
    const __nv_bfloat16* Wlo = Wlo0 + (size_t)blockIdx.y * 16384;
    float* C = C0 ? (C0 + (size_t)blockIdx.y * (size_t)N_NODES * EMB) : (float*)0;

    int tid = threadIdx.x;
    int wid = tid >> 5;
    int lane = tid & 31;
    int wm = wid & 1;        // 0..1 -> m half (64 rows)
    int wn = wid >> 1;       // 0..3 -> n quarter (32 cols)
    int r0 = blockIdx.x * 128;

    uint32_t as_base = smem_u32(As);
    uint32_t bs_base = smem_u32(Bs);

    float acc[4][4][4];
#pragma unroll
    for (int i = 0; i < 4; i++)
#pragma unroll
        for (int j = 0; j < 4; j++)
#pragma unroll
            for (int q = 0; q < 4; q++) acc[i][j][q] = 0.0f;

    // ldmatrix lane address components
    int l_within = lane & 7;
    int l_sel = lane >> 3;     // 0..3

    for (int pass = 0; pass < 3; pass++) {
        const __nv_bfloat16* Asrc = (pass == 2) ? Alo : Ahi;
        const __nv_bfloat16* Bsrc = (pass == 1) ? Wlo : Whi;
        for (int k0 = 0; k0 < K; k0 += BK) {
            __syncthreads();
            // load A tile: 128 rows x 32 cols bf16 -> 512 x 16B, 2 per thread
#pragma unroll
            for (int i = 0; i < 2; i++) {
                int idx = tid * 2 + i;
                int row = idx >> 2;
                int ch = idx & 3;
                uint4 v = make_uint4(0, 0, 0, 0);
                int gr = r0 + row;
                if (gr < M)
                    v = *(const uint4*)(Asrc + (size_t)gr * K + k0 + ch * 8);
                *(uint4*)(&As[row * SSTR + ch * 8]) = v;
            }
            // load B tile: 128 n-rows x 32 k-cols (W row stride = 128 elems always)
#pragma unroll
            for (int i = 0; i < 2; i++) {
                int idx = tid * 2 + i;
                int row = idx >> 2;
                int ch = idx & 3;
                uint4 v = *(const uint4*)(Bsrc + (size_t)row * 128 + k0 + ch * 8);
                *(uint4*)(&Bs[row * SSTR + ch * 8]) = v;
            }
            __syncthreads();

#pragma unroll
            for (int ks = 0; ks < 2; ks++) {
                uint32_t af[4][4];
                uint32_t bf[4][2];
                // A fragments: 4 x (16x16 tile) via ldmatrix.x4
#pragma unroll
                for (int fm = 0; fm < 4; fm++) {
                    int arow = wm * 64 + fm * 16 + (l_sel & 1) * 8 + l_within;
                    int acol = ks * 16 + (l_sel >> 1) * 8;
                    ldsm4(af[fm][0], af[fm][1], af[fm][2], af[fm][3],
                          as_base + (uint32_t)(arow * SSTR + acol) * 2u);
                }
                // B fragments: 2 x ldmatrix.x4, each covering 2 n-frags
#pragma unroll
                for (int g = 0; g < 2; g++) {
                    int brow = wn * 32 + g * 16 + (l_sel >> 1) * 8 + l_within;
                    int bcol = ks * 16 + (l_sel & 1) * 8;
                    uint32_t r0v, r1v, r2v, r3v;
                    ldsm4(r0v, r1v, r2v, r3v,
                          bs_base + (uint32_t)(brow * SSTR + bcol) * 2u);
                    bf[2 * g + 0][0] = r0v; bf[2 * g + 0][1] = r1v;
                    bf[2 * g + 1][0] = r2v; bf[2 * g + 1][1] = r3v;
                }
#pragma unroll
                for (int fm = 0; fm < 4; fm++)
#pragma unroll
                    for (int fn = 0; fn < 4; fn++)
                        mma16816(acc[fm][fn], af[fm], bf[fn]);
            }
        }
    }

    // epilogue
    int qrow = lane >> 2;
    int qcol = (lane & 3) * 2;
#pragma unroll
    for (int fm = 0; fm < 4; fm++) {
#pragma unroll
        for (int half = 0; half < 2; half++) {
            int grow = r0 + wm * 64 + fm * 16 + qrow + half * 8;
            if (grow >= M) continue;
#pragma unroll
            for (int fn = 0; fn < 4; fn++) {
                int col = wn * 32 + fn * 8 + qcol;
                float v0 = acc[fm][fn][half * 2 + 0];
                float v1 = acc[fm][fn][half * 2 + 1];
                if (bias) {
                    v0 += __ldg(&bias[col]);
                    v1 += __ldg(&bias[col + 1]);
                }
                if (C) {
                    float2 fv; fv.x = v0; fv.y = v1;
                    *(float2*)(C + (size_t)grow * EMB + col) = fv;
                }
                if (Ohi) {
                    __nv_bfloat16 h0 = __float2bfloat16(v0);
                    __nv_bfloat16 h1 = __float2bfloat16(v1);
                    __nv_bfloat162 hp; hp.x = h0; hp.y = h1;
                    __nv_bfloat162 lp;
                    lp.x = __float2bfloat16(v0 - __bfloat162float(h0));
                    lp.y = __float2bfloat16(v1 - __bfloat162float(h1));
                    *(__nv_bfloat162*)(Ohi + (size_t)grow * EMB + col) = hp;
                    *(__nv_bfloat162*)(Olo + (size_t)grow * EMB + col) = lp;
                }
            }
        }
    }
}

// ---------------- aggregation: out[n] += max over incoming edges of msg[src] ----------------
// On last relation: relu, write h fp32 and its bf16 hi/lo split for the next layer.
__global__ __launch_bounds__(128) void aggregate_kernel(
    const float* __restrict__ msg, const int* __restrict__ off,
    const int* __restrict__ csr, float* __restrict__ outbuf,
    float* __restrict__ hOut,
    __nv_bfloat16* __restrict__ h_hi, __nv_bfloat16* __restrict__ h_lo,
    int do_relu)
{
    int nIdx = blockIdx.x;
    int f = threadIdx.x;
    int s = off[nIdx];
    int e = off[nIdx + 1];
    float m = -3.402823466e38f;
    for (int i = s; i < e; i++) {
        int src = __ldg(&csr[i]);
        m = fmaxf(m, __ldg(&msg[(size_t)src * EMB + f]));
    }
    float contrib = (e > s) ? m : 0.0f;
    size_t idx = (size_t)nIdx * EMB + f;
    float v = outbuf[idx] + contrib;
    if (do_relu) {
        v = fmaxf(v, 0.0f);
        hOut[idx] = v;
        __nv_bfloat16 h = __float2bfloat16(v);
        h_hi[idx] = h;
        h_lo[idx] = __float2bfloat16(v - __bfloat162float(h));
    } else {
        outbuf[idx] = v;
    }
}

// ---------------- global add pool ----------------
__global__ __launch_bounds__(128) void pool_kernel(
    const float* __restrict__ h, const int* __restrict__ batch,
    float* __restrict__ out, int n)
{
    const int NPB = 256;
    int f = threadIdx.x;
    int n0 = blockIdx.x * NPB;
    if (n0 >= n) return;
    int nend = min(n0 + NPB, n);
    float acc = 0.0f;
    int cur = batch[n0];
    for (int i = n0; i < nend; i++) {
        int b = batch[i];
        if (b != cur) {
            atomicAdd(&out[(size_t)cur * EMB + f], acc);
            acc = 0.0f;
            cur = b;
        }
        acc += h[(size_t)i * EMB + f];
    }
    atomicAdd(&out[(size_t)cur * EMB + f], acc);
}

// ---------------- host launch ----------------
extern "C" void kernel_launch(void* const* d_in, const int* in_sizes, int n_in,
                              void* d_out, int out_size)
{
    const float* x      = (const float*)d_in[0];
    const int*   ei[N_REL] = { (const int*)d_in[1], (const int*)d_in[2],
                               (const int*)d_in[3], (const int*)d_in[4] };
    const int*   batch  = (const int*)d_in[5];
    const float* emb_w  = (const float*)d_in[6];
    const float* emb_b  = (const float*)d_in[7];
    const float* root_w = (const float*)d_in[8];
    const float* root_b = (const float*)d_in[9];
    const float* conv_w = (const float*)d_in[10];
    float* out = (float*)d_out;

    void *p_h, *p_out, *p_tmp, *p_hhi, *p_hlo, *p_xhi, *p_xlo, *p_whi, *p_wlo;
    void *p_csr, *p_deg, *p_off, *p_cur;
    cudaGetSymbolAddress(&p_h, g_h);
    cudaGetSymbolAddress(&p_out, g_out);
    cudaGetSymbolAddress(&p_tmp, g_tmp);
    cudaGetSymbolAddress(&p_hhi, g_h_hi);
    cudaGetSymbolAddress(&p_hlo, g_h_lo);
    cudaGetSymbolAddress(&p_xhi, g_x_hi);
    cudaGetSymbolAddress(&p_xlo, g_x_lo);
    cudaGetSymbolAddress(&p_whi, g_w_hi);
    cudaGetSymbolAddress(&p_wlo, g_w_lo);
    cudaGetSymbolAddress(&p_csr, g_csr_src);
    cudaGetSymbolAddress(&p_deg, g_deg);
    cudaGetSymbolAddress(&p_off, g_off);
    cudaGetSymbolAddress(&p_cur, g_cur);
    float* h_buf   = (float*)p_h;
    float* out_buf = (float*)p_out;
    float* tmp_buf = (float*)p_tmp;
    __nv_bfloat16* h_hi = (__nv_bfloat16*)p_hhi;
    __nv_bfloat16* h_lo = (__nv_bfloat16*)p_hlo;
    __nv_bfloat16* x_hi = (__nv_bfloat16*)p_xhi;
    __nv_bfloat16* x_lo = (__nv_bfloat16*)p_xlo;
    __nv_bfloat16* w_hi = (__nv_bfloat16*)p_whi;
    __nv_bfloat16* w_lo = (__nv_bfloat16*)p_wlo;
    int* csr = (int*)p_csr;
    int* deg = (int*)p_deg;
    int* off = (int*)p_off;
    int* cur = (int*)p_cur;

    const int EB = (N_EDGES + 255) / 256;
    const int GB = (N_NODES + 127) / 128;   // 782 M-tiles
    const size_t MN = (size_t)N_NODES * EMB;

    // ---- weight + x bf16 splits ----
    split_w_kernel<<<(21 * 128 * 128 + 255) / 256, 256>>>(emb_w, root_w, conv_w, w_hi, w_lo);
    split_x_kernel<<<(N_NODES * IN_FEAT + 255) / 256, 256>>>(x, x_hi, x_lo, N_NODES * IN_FEAT);

    // ---- CSR build (per relation) ----
    zero_int_kernel<<<(N_REL * N_NODES + 255) / 256, 256>>>(deg, N_REL * N_NODES);
    for (int r = 0; r < N_REL; r++)
        hist_kernel<<<EB, 256>>>(ei[r] + N_EDGES, deg + (size_t)r * N_NODES, N_EDGES);
    for (int r = 0; r < N_REL; r++)
        scan_kernel<<<1, 1024>>>(deg + (size_t)r * N_NODES,
                                 off + (size_t)r * (N_NODES + 1), N_NODES);
    for (int r = 0; r < N_REL; r++)
        copy_int_kernel<<<(N_NODES + 255) / 256, 256>>>(
            off + (size_t)r * (N_NODES + 1), cur + (size_t)r * N_NODES, N_NODES);
    for (int r = 0; r < N_REL; r++)
        fill_kernel<<<EB, 256>>>(ei[r], ei[r] + N_EDGES,
                                 cur + (size_t)r * N_NODES,
                                 csr + (size_t)r * N_EDGES, N_EDGES);

    // ---- embed: h = x @ emb_w + emb_b -> bf16 hi/lo only ----
    gemm_mma<<<GB, 256>>>(x_hi, x_lo, N_NODES, IN_FEAT,
                          w_hi, w_lo, emb_b,
                          (float*)0, h_hi, h_lo);

    // ---- layers ----
    for (int l = 0; l < N_LAYERS; l++) {
        // root: out = h @ root_w[l] + root_b[l]
        gemm_mma<<<GB, 256>>>(h_hi, h_lo, N_NODES, EMB,
                              w_hi + (size_t)(1 + l) * 16384,
                              w_lo + (size_t)(1 + l) * 16384,
                              root_b + (size_t)l * EMB,
                              out_buf, (__nv_bfloat16*)0, (__nv_bfloat16*)0);
        // 4 relation GEMMs batched: tmp[r] = h @ conv_w[l,r]
        gemm_mma<<<dim3(GB, N_REL), 256>>>(h_hi, h_lo, N_NODES, EMB,
                                           w_hi + (size_t)(5 + l * N_REL) * 16384,
                                           w_lo + (size_t)(5 + l * N_REL) * 16384,
                                           (const float*)0,
                                           tmp_buf, (__nv_bfloat16*)0, (__nv_bfloat16*)0);
        for (int r = 0; r < N_REL; r++)
            aggregate_kernel<<<N_NODES, 128>>>(
                tmp_buf + (size_t)r * MN, off + (size_t)r * (N_NODES + 1),
                csr + (size_t)r * N_EDGES, out_buf, h_buf,
                h_hi, h_lo, (r == N_REL - 1) ? 1 : 0);
    }

    // ---- global add pool ----
    zero_float_kernel<<<(N_GRAPHS * EMB + 255) / 256, 256>>>(out, N_GRAPHS * EMB);
    pool_kernel<<<(N_NODES + 255) / 256, 128>>>(h_buf, batch, out, N_NODES);
}

// round 6
// speedup vs baseline: 2.3547x; 2.0257x over previous
#include <cuda_runtime.h>
#include <cuda_bf16.h>
#include <cstdint>
#include <cfloat>

#define N_NODES 100000
#define N_EDGES 500000
#define N_REL 4
#define N_LAYERS 4
#define IN_FEAT 64
#define EMB 128
#define N_GRAPHS 64
#define SCAN_NB 98   // ceil(100000/1024)

// ---------------- scratch (device globals; no allocation allowed) ----------------
__device__ float g_h[(size_t)N_NODES * EMB];                 // final-layer h (for pool)
__device__ float g_out[(size_t)N_NODES * EMB];               // root accumulator
__device__ float g_tmp[(size_t)N_REL * N_NODES * EMB];       // per-relation conv outputs
__device__ __nv_bfloat16 g_h_hi[(size_t)N_NODES * EMB];
__device__ __nv_bfloat16 g_h_lo[(size_t)N_NODES * EMB];
__device__ __nv_bfloat16 g_x_hi[(size_t)N_NODES * IN_FEAT];
__device__ __nv_bfloat16 g_x_lo[(size_t)N_NODES * IN_FEAT];
// 21 weight matrices, transposed [N=128][K=128] bf16 (k contiguous):
// slot 0 = emb (K rows 64..127 zero), 1..4 = root, 5..20 = conv (l*4+r)
__device__ __nv_bfloat16 g_w_hi[(size_t)21 * 128 * 128];
__device__ __nv_bfloat16 g_w_lo[(size_t)21 * 128 * 128];
__device__ int   g_csr_src[(size_t)N_REL * N_EDGES];
__device__ int   g_deg[(size_t)N_REL * N_NODES];
__device__ int   g_off[(size_t)N_REL * (N_NODES + 1)];
__device__ int   g_cur[(size_t)N_REL * N_NODES];
__device__ int   g_bsum[(size_t)N_REL * 128];

// ---------------- warp-mma helpers (baseline PTX; valid at compute_103) ----------------
__device__ __forceinline__ uint32_t smem_u32(const void* p) {
    uint32_t a;
    asm("{ .reg .u64 t; cvta.to.shared.u64 t, %1; cvt.u32.u64 %0, t; }" : "=r"(a) : "l"(p));
    return a;
}
__device__ __forceinline__ void ldsm4(uint32_t& r0, uint32_t& r1, uint32_t& r2, uint32_t& r3,
                                      uint32_t addr) {
    asm volatile("ldmatrix.sync.aligned.m8n8.x4.shared.b16 {%0,%1,%2,%3}, [%4];"
                 : "=r"(r0), "=r"(r1), "=r"(r2), "=r"(r3) : "r"(addr));
}
__device__ __forceinline__ void mma16816(float* d, const uint32_t* a, const uint32_t* b) {
    asm volatile(
        "mma.sync.aligned.m16n8k16.row.col.f32.bf16.bf16.f32 "
        "{%0,%1,%2,%3}, {%4,%5,%6,%7}, {%8,%9}, {%0,%1,%2,%3};"
        : "+f"(d[0]), "+f"(d[1]), "+f"(d[2]), "+f"(d[3])
        : "r"(a[0]), "r"(a[1]), "r"(a[2]), "r"(a[3]), "r"(b[0]), "r"(b[1]));
}

// ---------------- utility kernels ----------------
__global__ void zero_int_kernel(int* p, int n) {
    int i = blockIdx.x * blockDim.x + threadIdx.x;
    if (i < n) p[i] = 0;
}
__global__ void zero_float_kernel(float* p, int n) {
    int i = blockIdx.x * blockDim.x + threadIdx.x;
    if (i < n) p[i] = 0.0f;
}

// fused histogram over all 4 relations (blockIdx.y = relation)
__global__ void hist_all_kernel(const int* __restrict__ e0, const int* __restrict__ e1,
                                const int* __restrict__ e2, const int* __restrict__ e3,
                                int* __restrict__ deg) {
    int r = blockIdx.y;
    const int* dst = ((r == 0) ? e0 : (r == 1) ? e1 : (r == 2) ? e2 : e3) + N_EDGES;
    int i = blockIdx.x * 256 + threadIdx.x;
    if (i < N_EDGES) atomicAdd(&deg[(size_t)r * N_NODES + dst[i]], 1);
}

// -------- 3-phase parallel exclusive scan of deg -> off (all relations) --------
__global__ void scan_p1(const int* __restrict__ deg, int* __restrict__ bsum) {
    int r = blockIdx.y, b = blockIdx.x, t = threadIdx.x;
    const int* d = deg + (size_t)r * N_NODES;
    int base = b * 1024 + t * 4;
    int s = 0;
#pragma unroll
    for (int j = 0; j < 4; j++) {
        int idx = base + j;
        if (idx < N_NODES) s += d[idx];
    }
    __shared__ int sm[256];
    sm[t] = s;
    __syncthreads();
    for (int o = 128; o > 0; o >>= 1) {
        if (t < o) sm[t] += sm[t + o];
        __syncthreads();
    }
    if (t == 0) bsum[r * 128 + b] = sm[0];
}
__global__ void scan_p2(int* __restrict__ bsum) {
    __shared__ int sm[512];
    int t = threadIdx.x;
    int r = t >> 7;
    int i = t & 127;
    int v = (i < SCAN_NB) ? bsum[r * 128 + i] : 0;
    sm[t] = v;
    __syncthreads();
    for (int d = 1; d < 128; d <<= 1) {
        int add = (i >= d) ? sm[t - d] : 0;
        __syncthreads();
        sm[t] += add;
        __syncthreads();
    }
    int excl = (i == 0) ? 0 : sm[t - 1];
    if (i < SCAN_NB) bsum[r * 128 + i] = excl;
}
__global__ void scan_p3(const int* __restrict__ deg, const int* __restrict__ bsum,
                        int* __restrict__ off, int* __restrict__ cur) {
    int r = blockIdx.y, b = blockIdx.x, t = threadIdx.x;
    const int* d = deg + (size_t)r * N_NODES;
    int* o = off + (size_t)r * (N_NODES + 1);
    int* c = cur + (size_t)r * N_NODES;
    int base = b * 1024 + t * 4;
    int v[4], pre[4];
    int s = 0;
#pragma unroll
    for (int j = 0; j < 4; j++) {
        int idx = base + j;
        v[j] = (idx < N_NODES) ? d[idx] : 0;
        pre[j] = s;
        s += v[j];
    }
    __shared__ int sm[256];
    sm[t] = s;
    __syncthreads();
    for (int dd = 1; dd < 256; dd <<= 1) {
        int add = (t >= dd) ? sm[t - dd] : 0;
        __syncthreads();
        sm[t] += add;
        __syncthreads();
    }
    int texcl = (t == 0) ? 0 : sm[t - 1];
    int boff = bsum[r * 128 + b];
#pragma unroll
    for (int j = 0; j < 4; j++) {
        int idx = base + j;
        if (idx < N_NODES) {
            int val = boff + texcl + pre[j];
            o[idx] = val;
            c[idx] = val;
        }
    }
    if (b == SCAN_NB - 1 && t == 255) o[N_NODES] = boff + sm[255];
}

__global__ void fill_all_kernel(const int* __restrict__ e0, const int* __restrict__ e1,
                                const int* __restrict__ e2, const int* __restrict__ e3,
                                int* __restrict__ cur, int* __restrict__ csr) {
    int r = blockIdx.y;
    const int* eptr = (r == 0) ? e0 : (r == 1) ? e1 : (r == 2) ? e2 : e3;
    int i = blockIdx.x * 256 + threadIdx.x;
    if (i < N_EDGES) {
        int dnode = eptr[N_EDGES + i];
        int pos = atomicAdd(&cur[(size_t)r * N_NODES + dnode], 1);
        csr[(size_t)r * N_EDGES + pos] = eptr[i];
    }
}

// ---------------- fp32 -> bf16 hi/lo split kernels ----------------
__global__ void split_x_kernel(const float* __restrict__ x,
                               __nv_bfloat16* __restrict__ hi,
                               __nv_bfloat16* __restrict__ lo, int n) {
    int i = blockIdx.x * blockDim.x + threadIdx.x;
    if (i >= n) return;
    float v = x[i];
    __nv_bfloat16 h = __float2bfloat16(v);
    hi[i] = h;
    lo[i] = __float2bfloat16(v - __bfloat162float(h));
}
__global__ void split_w_kernel(const float* __restrict__ emb_w,
                               const float* __restrict__ root_w,
                               const float* __restrict__ conv_w,
                               __nv_bfloat16* __restrict__ whi,
                               __nv_bfloat16* __restrict__ wlo) {
    int idx = blockIdx.x * blockDim.x + threadIdx.x;
    if (idx >= 21 * 128 * 128) return;
    int s = idx >> 14;
    int rem = idx & 16383;
    int n = rem >> 7;
    int k = rem & 127;
    float v;
    if (s == 0)      v = (k < IN_FEAT) ? emb_w[(size_t)k * EMB + n] : 0.0f;
    else if (s <= 4) v = root_w[((size_t)(s - 1) * EMB + k) * EMB + n];
    else             v = conv_w[((size_t)(s - 5) * EMB + k) * EMB + n];
    __nv_bfloat16 h = __float2bfloat16(v);
    whi[idx] = h;
    wlo[idx] = __float2bfloat16(v - __bfloat162float(h));
}

// ---------------- bf16x3 mma.sync GEMM ----------------
// blockIdx.y: 0 -> root slot (slot0, bias, writes C_root [+ hi/lo split if Ohi]),
//             1..4 -> conv slot conv_base+y-1, writes C_tmp + (y-1)*M*N.
#define BK 32
#define SSTR 40

__global__ __launch_bounds__(256, 2) void gemm_mma(
    const __nv_bfloat16* __restrict__ Ahi, const __nv_bfloat16* __restrict__ Alo,
    int M, int K,
    const __nv_bfloat16* __restrict__ whi_base, const __nv_bfloat16* __restrict__ wlo_base,
    int slot0, int conv_base,
    const float* __restrict__ bias0,
    float* __restrict__ C_root, float* __restrict__ C_tmp,
    __nv_bfloat16* __restrict__ Ohi, __nv_bfloat16* __restrict__ Olo)
{
    __shared__ __nv_bfloat16 As[128 * SSTR];
    __shared__ __nv_bfloat16 Bs[128 * SSTR];

    int y = blockIdx.y;
    int slot = (y == 0) ? slot0 : (conv_base + y - 1);
    const __nv_bfloat16* Whi = whi_base + (size_t)slot * 16384;
    const __nv_bfloat16* Wlo = wlo_base + (size_t)slot * 16384;
    const float* bias = (y == 0) ? bias0 : (const float*)0;
    float* C = (y == 0) ? C_root : (C_tmp + (size_t)(y - 1) * (size_t)N_NODES * EMB);
    __nv_bfloat16* OhiL = (y == 0) ? Ohi : (__nv_bfloat16*)0;
    __nv_bfloat16* OloL = (y == 0) ? Olo : (__nv_bfloat16*)0;

    int tid = threadIdx.x;
    int wid = tid >> 5;
    int lane = tid & 31;
    int wm = wid & 1;
    int wn = wid >> 1;
    int r0 = blockIdx.x * 128;

    uint32_t as_base = smem_u32(As);
    uint32_t bs_base = smem_u32(Bs);

    float acc[4][4][4];
#pragma unroll
    for (int i = 0; i < 4; i++)
#pragma unroll
        for (int j = 0; j < 4; j++)
#pragma unroll
            for (int q = 0; q < 4; q++) acc[i][j][q] = 0.0f;

    int l_within = lane & 7;
    int l_sel = lane >> 3;

    for (int pass = 0; pass < 3; pass++) {
        const __nv_bfloat16* Asrc = (pass == 2) ? Alo : Ahi;
        const __nv_bfloat16* Bsrc = (pass == 1) ? Wlo : Whi;
        for (int k0 = 0; k0 < K; k0 += BK) {
            __syncthreads();
#pragma unroll
            for (int i = 0; i < 2; i++) {
                int idx = tid * 2 + i;
                int row = idx >> 2;
                int ch = idx & 3;
                uint4 v = make_uint4(0, 0, 0, 0);
                int gr = r0 + row;
                if (gr < M)
                    v = *(const uint4*)(Asrc + (size_t)gr * K + k0 + ch * 8);
                *(uint4*)(&As[row * SSTR + ch * 8]) = v;
            }
#pragma unroll
            for (int i = 0; i < 2; i++) {
                int idx = tid * 2 + i;
                int row = idx >> 2;
                int ch = idx & 3;
                uint4 v = *(const uint4*)(Bsrc + (size_t)row * 128 + k0 + ch * 8);
                *(uint4*)(&Bs[row * SSTR + ch * 8]) = v;
            }
            __syncthreads();

#pragma unroll
            for (int ks = 0; ks < 2; ks++) {
                uint32_t af[4][4];
                uint32_t bf[4][2];
#pragma unroll
                for (int fm = 0; fm < 4; fm++) {
                    int arow = wm * 64 + fm * 16 + (l_sel & 1) * 8 + l_within;
                    int acol = ks * 16 + (l_sel >> 1) * 8;
                    ldsm4(af[fm][0], af[fm][1], af[fm][2], af[fm][3],
                          as_base + (uint32_t)(arow * SSTR + acol) * 2u);
                }
#pragma unroll
                for (int g = 0; g < 2; g++) {
                    int brow = wn * 32 + g * 16 + (l_sel >> 1) * 8 + l_within;
                    int bcol = ks * 16 + (l_sel & 1) * 8;
                    uint32_t r0v, r1v, r2v, r3v;
                    ldsm4(r0v, r1v, r2v, r3v,
                          bs_base + (uint32_t)(brow * SSTR + bcol) * 2u);
                    bf[2 * g + 0][0] = r0v; bf[2 * g + 0][1] = r1v;
                    bf[2 * g + 1][0] = r2v; bf[2 * g + 1][1] = r3v;
                }
#pragma unroll
                for (int fm = 0; fm < 4; fm++)
#pragma unroll
                    for (int fn = 0; fn < 4; fn++)
                        mma16816(acc[fm][fn], af[fm], bf[fn]);
            }
        }
    }

    int qrow = lane >> 2;
    int qcol = (lane & 3) * 2;
#pragma unroll
    for (int fm = 0; fm < 4; fm++) {
#pragma unroll
        for (int half = 0; half < 2; half++) {
            int grow = r0 + wm * 64 + fm * 16 + qrow + half * 8;
            if (grow >= M) continue;
#pragma unroll
            for (int fn = 0; fn < 4; fn++) {
                int col = wn * 32 + fn * 8 + qcol;
                float v0 = acc[fm][fn][half * 2 + 0];
                float v1 = acc[fm][fn][half * 2 + 1];
                if (bias) {
                    v0 += __ldg(&bias[col]);
                    v1 += __ldg(&bias[col + 1]);
                }
                if (C) {
                    float2 fv; fv.x = v0; fv.y = v1;
                    *(float2*)(C + (size_t)grow * EMB + col) = fv;
                }
                if (OhiL) {
                    __nv_bfloat16 h0 = __float2bfloat16(v0);
                    __nv_bfloat16 h1 = __float2bfloat16(v1);
                    __nv_bfloat162 hp; hp.x = h0; hp.y = h1;
                    __nv_bfloat162 lp;
                    lp.x = __float2bfloat16(v0 - __bfloat162float(h0));
                    lp.y = __float2bfloat16(v1 - __bfloat162float(h1));
                    *(__nv_bfloat162*)(OhiL + (size_t)grow * EMB + col) = hp;
                    *(__nv_bfloat162*)(OloL + (size_t)grow * EMB + col) = lp;
                }
            }
        }
    }
}

// ---------------- fused per-layer aggregation ----------------
// warp-per-node: lane l handles features [4l, 4l+4). Loops all 4 relations,
// max-gathers from tmp[r], adds to root result, relu, writes bf16 hi/lo
// (and fp32 h when write_f32 != 0, i.e. last layer for pooling).
__global__ __launch_bounds__(256) void agg_fused_kernel(
    const float* __restrict__ tmp, const int* __restrict__ off,
    const int* __restrict__ csr, const float* __restrict__ rootv,
    float* __restrict__ hOut,
    __nv_bfloat16* __restrict__ h_hi, __nv_bfloat16* __restrict__ h_lo,
    int write_f32)
{
    int node = blockIdx.x * 8 + (threadIdx.x >> 5);
    if (node >= N_NODES) return;
    int lane = threadIdx.x & 31;
    size_t base = (size_t)node * EMB + lane * 4;

    float4 acc = *(const float4*)(rootv + base);

    int s[N_REL], e[N_REL];
#pragma unroll
    for (int r = 0; r < N_REL; r++) {
        const int* offr = off + (size_t)r * (N_NODES + 1);
        s[r] = __ldg(&offr[node]);
        e[r] = __ldg(&offr[node + 1]);
    }

#pragma unroll
    for (int r = 0; r < N_REL; r++) {
        const int* csrr = csr + (size_t)r * N_EDGES;
        const float* msg = tmp + (size_t)r * (size_t)N_NODES * EMB;
        int i = s[r];
        int ecnt = e[r];
        if (i < ecnt) {
            float4 m = make_float4(-FLT_MAX, -FLT_MAX, -FLT_MAX, -FLT_MAX);
            int src_next = __ldg(&csrr[i]);
            while (i < ecnt) {
                int src = src_next;
                if (i + 1 < ecnt) src_next = __ldg(&csrr[i + 1]);
                float4 v = *(const float4*)(msg + (size_t)src * EMB + lane * 4);
                m.x = fmaxf(m.x, v.x);
                m.y = fmaxf(m.y, v.y);
                m.z = fmaxf(m.z, v.z);
                m.w = fmaxf(m.w, v.w);
                i++;
            }
            acc.x += m.x; acc.y += m.y; acc.z += m.z; acc.w += m.w;
        }
    }

    acc.x = fmaxf(acc.x, 0.0f);
    acc.y = fmaxf(acc.y, 0.0f);
    acc.z = fmaxf(acc.z, 0.0f);
    acc.w = fmaxf(acc.w, 0.0f);

    if (write_f32) *(float4*)(hOut + base) = acc;

    __nv_bfloat16 h0 = __float2bfloat16(acc.x);
    __nv_bfloat16 h1 = __float2bfloat16(acc.y);
    __nv_bfloat16 h2 = __float2bfloat16(acc.z);
    __nv_bfloat16 h3 = __float2bfloat16(acc.w);
    __nv_bfloat162 hp0; hp0.x = h0; hp0.y = h1;
    __nv_bfloat162 hp1; hp1.x = h2; hp1.y = h3;
    __nv_bfloat162 lp0, lp1;
    lp0.x = __float2bfloat16(acc.x - __bfloat162float(h0));
    lp0.y = __float2bfloat16(acc.y - __bfloat162float(h1));
    lp1.x = __float2bfloat16(acc.z - __bfloat162float(h2));
    lp1.y = __float2bfloat16(acc.w - __bfloat162float(h3));
    *(__nv_bfloat162*)(h_hi + base) = hp0;
    *(__nv_bfloat162*)(h_hi + base + 2) = hp1;
    *(__nv_bfloat162*)(h_lo + base) = lp0;
    *(__nv_bfloat162*)(h_lo + base + 2) = lp1;
}

// ---------------- global add pool ----------------
__global__ __launch_bounds__(128) void pool_kernel(
    const float* __restrict__ h, const int* __restrict__ batch,
    float* __restrict__ out, int n)
{
    const int NPB = 256;
    int f = threadIdx.x;
    int n0 = blockIdx.x * NPB;
    if (n0 >= n) return;
    int nend = min(n0 + NPB, n);
    float acc = 0.0f;
    int cur = batch[n0];
    for (int i = n0; i < nend; i++) {
        int b = batch[i];
        if (b != cur) {
            atomicAdd(&out[(size_t)cur * EMB + f], acc);
            acc = 0.0f;
            cur = b;
        }
        acc += h[(size_t)i * EMB + f];
    }
    atomicAdd(&out[(size_t)cur * EMB + f], acc);
}

// ---------------- host launch ----------------
extern "C" void kernel_launch(void* const* d_in, const int* in_sizes, int n_in,
                              void* d_out, int out_size)
{
    const float* x      = (const float*)d_in[0];
    const int*   e0     = (const int*)d_in[1];
    const int*   e1     = (const int*)d_in[2];
    const int*   e2     = (const int*)d_in[3];
    const int*   e3     = (const int*)d_in[4];
    const int*   batch  = (const int*)d_in[5];
    const float* emb_w  = (const float*)d_in[6];
    const float* emb_b  = (const float*)d_in[7];
    const float* root_w = (const float*)d_in[8];
    const float* root_b = (const float*)d_in[9];
    const float* conv_w = (const float*)d_in[10];
    float* out = (float*)d_out;

    void *p_h, *p_out, *p_tmp, *p_hhi, *p_hlo, *p_xhi, *p_xlo, *p_whi, *p_wlo;
    void *p_csr, *p_deg, *p_off, *p_cur, *p_bsum;
    cudaGetSymbolAddress(&p_h, g_h);
    cudaGetSymbolAddress(&p_out, g_out);
    cudaGetSymbolAddress(&p_tmp, g_tmp);
    cudaGetSymbolAddress(&p_hhi, g_h_hi);
    cudaGetSymbolAddress(&p_hlo, g_h_lo);
    cudaGetSymbolAddress(&p_xhi, g_x_hi);
    cudaGetSymbolAddress(&p_xlo, g_x_lo);
    cudaGetSymbolAddress(&p_whi, g_w_hi);
    cudaGetSymbolAddress(&p_wlo, g_w_lo);
    cudaGetSymbolAddress(&p_csr, g_csr_src);
    cudaGetSymbolAddress(&p_deg, g_deg);
    cudaGetSymbolAddress(&p_off, g_off);
    cudaGetSymbolAddress(&p_cur, g_cur);
    cudaGetSymbolAddress(&p_bsum, g_bsum);
    float* h_buf   = (float*)p_h;
    float* out_buf = (float*)p_out;
    float* tmp_buf = (float*)p_tmp;
    __nv_bfloat16* h_hi = (__nv_bfloat16*)p_hhi;
    __nv_bfloat16* h_lo = (__nv_bfloat16*)p_hlo;
    __nv_bfloat16* x_hi = (__nv_bfloat16*)p_xhi;
    __nv_bfloat16* x_lo = (__nv_bfloat16*)p_xlo;
    __nv_bfloat16* w_hi = (__nv_bfloat16*)p_whi;
    __nv_bfloat16* w_lo = (__nv_bfloat16*)p_wlo;
    int* csr = (int*)p_csr;
    int* deg = (int*)p_deg;
    int* off = (int*)p_off;
    int* cur = (int*)p_cur;
    int* bsum = (int*)p_bsum;

    const int EB = (N_EDGES + 255) / 256;
    const int GB = (N_NODES + 127) / 128;
    const int AB = (N_NODES + 7) / 8;       // agg blocks (8 nodes each)

    // launches 0-1: splits
    split_w_kernel<<<(21 * 128 * 128 + 255) / 256, 256>>>(emb_w, root_w, conv_w, w_hi, w_lo);
    split_x_kernel<<<(N_NODES * IN_FEAT + 255) / 256, 256>>>(x, x_hi, x_lo, N_NODES * IN_FEAT);
    // launch 2-3: degree histogram
    zero_int_kernel<<<(N_REL * N_NODES + 255) / 256, 256>>>(deg, N_REL * N_NODES);
    hist_all_kernel<<<dim3(EB, N_REL), 256>>>(e0, e1, e2, e3, deg);
    // launch 4: embed GEMM  h = x @ emb_w + emb_b  (hi/lo split only)
    gemm_mma<<<dim3(GB, 1), 256>>>(x_hi, x_lo, N_NODES, IN_FEAT, w_hi, w_lo,
                                   0, 0, emb_b, (float*)0, tmp_buf, h_hi, h_lo);
    // launch 5 (ncu-profiled): layer-0 fused root+conv GEMM
    gemm_mma<<<dim3(GB, 5), 256>>>(h_hi, h_lo, N_NODES, EMB, w_hi, w_lo,
                                   1, 5, root_b, out_buf, tmp_buf,
                                   (__nv_bfloat16*)0, (__nv_bfloat16*)0);
    // launches 6-9: CSR build
    scan_p1<<<dim3(SCAN_NB, N_REL), 256>>>(deg, bsum);
    scan_p2<<<1, 512>>>(bsum);
    scan_p3<<<dim3(SCAN_NB, N_REL), 256>>>(deg, bsum, off, cur);
    fill_all_kernel<<<dim3(EB, N_REL), 256>>>(e0, e1, e2, e3, cur, csr);
    // launch 10: layer-0 aggregation
    agg_fused_kernel<<<AB, 256>>>(tmp_buf, off, csr, out_buf, h_buf, h_hi, h_lo, 0);
    // layers 1..3
    for (int l = 1; l < N_LAYERS; l++) {
        gemm_mma<<<dim3(GB, 5), 256>>>(h_hi, h_lo, N_NODES, EMB, w_hi, w_lo,
                                       1 + l, 5 + l * N_REL, root_b + (size_t)l * EMB,
                                       out_buf, tmp_buf,
                                       (__nv_bfloat16*)0, (__nv_bfloat16*)0);
        agg_fused_kernel<<<AB, 256>>>(tmp_buf, off, csr, out_buf, h_buf, h_hi, h_lo,
                                      (l == N_LAYERS - 1) ? 1 : 0);
    }
    // pool
    zero_float_kernel<<<(N_GRAPHS * EMB + 255) / 256, 256>>>(out, N_GRAPHS * EMB);
    pool_kernel<<<(N_NODES + 255) / 256, 128>>>(h_buf, batch, out, N_NODES);
}